// round 3
// baseline (speedup 1.0000x reference)
#include <cuda_runtime.h>
#include <math_constants.h>

// Bidirectional Chamfer distance, B=4, N=M=4096, D=3, fp32.
// dist = |q|^2 + |t|^2 - 2 q.t
// One block = 256 queries x ALL 4096 targets (full per-query min locally),
// packed f32x2 FMA inner loop (2 targets / fma issue), fused block-sum,
// then a tiny 128-element final reduction. Deterministic (fixed sum order).

#define BATCH   4
#define NPTS    4096
#define THREADS 128
#define QPT     2                    // queries per thread
#define QBLK    (THREADS * QPT)      // 256 queries per block
#define NQBLK   (NPTS / QBLK)        // 16
#define NDIRB   (2 * BATCH)          // 8
#define NBLK    (NQBLK * NDIRB)      // 128 blocks
#define TTP     (NPTS / 2)           // 2048 target pairs (all targets)
#define SMEM_BYTES (2 * TTP * 16)    // 64 KB

__device__ float g_bsum[NBLK];

__global__ __launch_bounds__(THREADS, 1)
void chamfer_min_kernel(const float* __restrict__ src,
                        const float* __restrict__ tgt) {
    // dynamic smem: s_xy[TTP] then s_zw[TTP]
    //   s_xy[p] = (-2x0, -2x1, -2y0, -2y1)
    //   s_zw[p] = (-2z0, -2z1, |t0|^2, |t1|^2)
    extern __shared__ float4 smem[];
    float4* s_xy = smem;
    float4* s_zw = smem + TTP;

    const int bz  = blockIdx.y;     // 0..7 = b*2 + dir
    const int b   = bz >> 1;
    const int dir = bz & 1;

    const float* __restrict__ qbase = (dir ? tgt : src) + (size_t)b * NPTS * 3;
    const float* __restrict__ tbase = (dir ? src : tgt) + (size_t)b * NPTS * 3;

    // --- preprocess ALL targets into paired f32x2 layout (float4 gmem loads)
    // group g = 4 points = 3 float4 = 2 pairs
    {
        const float4* __restrict__ t4 = reinterpret_cast<const float4*>(tbase);
        for (int g = threadIdx.x; g < NPTS / 4; g += THREADS) {
            float4 A = t4[3 * g + 0];
            float4 Bv = t4[3 * g + 1];
            float4 C = t4[3 * g + 2];
            // points: (A.x,A.y,A.z) (A.w,B.x,B.y) (B.z,B.w,C.x) (C.y,C.z,C.w)
            s_xy[2 * g + 0] = make_float4(-2.0f * A.x, -2.0f * A.w,
                                          -2.0f * A.y, -2.0f * Bv.x);
            s_zw[2 * g + 0] = make_float4(-2.0f * A.z, -2.0f * Bv.y,
                fmaf(A.x, A.x, fmaf(A.y, A.y, A.z * A.z)),
                fmaf(A.w, A.w, fmaf(Bv.x, Bv.x, Bv.y * Bv.y)));
            s_xy[2 * g + 1] = make_float4(-2.0f * Bv.z, -2.0f * C.y,
                                          -2.0f * Bv.w, -2.0f * C.z);
            s_zw[2 * g + 1] = make_float4(-2.0f * C.x, -2.0f * C.w,
                fmaf(Bv.z, Bv.z, fmaf(Bv.w, Bv.w, C.x * C.x)),
                fmaf(C.y, C.y, fmaf(C.z, C.z, C.w * C.w)));
        }
    }
    __syncthreads();

    // --- load queries, broadcast-pack into f32x2 operands
    const int q0 = blockIdx.x * QBLK;
    unsigned long long qx2[QPT], qy2[QPT], qz2[QPT];
    float q2[QPT], mn[QPT];
#pragma unroll
    for (int j = 0; j < QPT; j++) {
        int q = q0 + threadIdx.x + j * THREADS;
        float x = qbase[q * 3 + 0];
        float y = qbase[q * 3 + 1];
        float z = qbase[q * 3 + 2];
        asm("mov.b64 %0, {%1, %1};" : "=l"(qx2[j]) : "f"(x));
        asm("mov.b64 %0, {%1, %1};" : "=l"(qy2[j]) : "f"(y));
        asm("mov.b64 %0, {%1, %1};" : "=l"(qz2[j]) : "f"(z));
        q2[j] = fmaf(x, x, fmaf(y, y, z * z));
        mn[j] = CUDART_INF_F;
    }

    const ulonglong2* __restrict__ pXY = reinterpret_cast<const ulonglong2*>(s_xy);
    const ulonglong2* __restrict__ pZW = reinterpret_cast<const ulonglong2*>(s_zw);

    // --- main loop: per target-pair: 6 FFMA2 (fma pipe) + 4 FMNMX (alu) + 2 LDS
#pragma unroll 8
    for (int p = 0; p < TTP; p++) {
        ulonglong2 xy = pXY[p];   // (x0,x1), (y0,y1)
        ulonglong2 zw = pZW[p];   // (z0,z1), (w0,w1)
#pragma unroll
        for (int j = 0; j < QPT; j++) {
            float s0, s1;
            asm("{\n\t"
                ".reg .b64 d;\n\t"
                "fma.rn.f32x2 d, %2, %3, %4;\n\t"
                "fma.rn.f32x2 d, %5, %6, d;\n\t"
                "fma.rn.f32x2 d, %7, %8, d;\n\t"
                "mov.b64 {%0, %1}, d;\n\t"
                "}"
                : "=f"(s0), "=f"(s1)
                : "l"(zw.x), "l"(qz2[j]), "l"(zw.y),
                  "l"(xy.y), "l"(qy2[j]),
                  "l"(xy.x), "l"(qx2[j]));
            mn[j] = fminf(fminf(mn[j], s0), s1);
        }
    }

    // --- fused block sum: sum_j (mn[j] + q2[j]) over all threads
    float local = (mn[0] + q2[0]) + (mn[1] + q2[1]);
#pragma unroll
    for (int off = 16; off > 0; off >>= 1)
        local += __shfl_down_sync(0xFFFFFFFFu, local, off);

    __shared__ float s_wsum[THREADS / 32];
    if ((threadIdx.x & 31) == 0) s_wsum[threadIdx.x >> 5] = local;
    __syncthreads();
    if (threadIdx.x == 0) {
        float bs = s_wsum[0] + s_wsum[1] + s_wsum[2] + s_wsum[3];
        g_bsum[blockIdx.y * NQBLK + blockIdx.x] = bs;
    }
}

// final: sum 128 block sums, divide. Single warp-per-lane deterministic.
__global__ __launch_bounds__(128)
void chamfer_final_kernel(float* __restrict__ out) {
    float v = g_bsum[threadIdx.x];
#pragma unroll
    for (int off = 16; off > 0; off >>= 1)
        v += __shfl_down_sync(0xFFFFFFFFu, v, off);
    __shared__ float s_w[4];
    if ((threadIdx.x & 31) == 0) s_w[threadIdx.x >> 5] = v;
    __syncthreads();
    if (threadIdx.x == 0)
        out[0] = (s_w[0] + s_w[1] + s_w[2] + s_w[3]) / (float)(BATCH * NPTS);
}

extern "C" void kernel_launch(void* const* d_in, const int* in_sizes, int n_in,
                              void* d_out, int out_size) {
    const float* src = (const float*)d_in[0];  // (B, N, 3)
    const float* tgt = (const float*)d_in[1];  // (B, M, 3)
    float* out = (float*)d_out;

    cudaFuncSetAttribute(chamfer_min_kernel,
                         cudaFuncAttributeMaxDynamicSharedMemorySize, SMEM_BYTES);

    dim3 grid(NQBLK, NDIRB);  // 16 x 8 = 128 blocks
    chamfer_min_kernel<<<grid, THREADS, SMEM_BYTES>>>(src, tgt);

    chamfer_final_kernel<<<1, 128>>>(out);
}